// round 1
// baseline (speedup 1.0000x reference)
#include <cuda_runtime.h>

// Problem constants (fixed by setup_inputs)
#define N_PTS 2048
#define N_C   1024
#define B_SZ  8
#define WARPS_PER_BLOCK 8
#define BLOCK_THREADS   256
#define CHUNKS_PER_BATCH (N_PTS / WARPS_PER_BLOCK)        // 256
#define NUM_BLOCKS (B_SZ * CHUNKS_PER_BATCH)              // 2048
#define N_TOTAL (B_SZ * N_PTS)                            // 16384

// Output layout (tuple concat): y_diff | x_diff | d_out(B,N,2) | x_n | y_n
#define OFF_YDIFF 0
#define OFF_XDIFF (N_TOTAL)
#define OFF_DOUT  (2 * N_TOTAL)
#define OFF_XN    (4 * N_TOTAL)
#define OFF_YN    (5 * N_TOTAL)

// Deterministic reduction scratch (no device allocation allowed)
__device__ double g_psum[NUM_BLOCKS];
__device__ double g_psum2[NUM_BLOCKS];
__device__ float  g_affine[2];   // scale, shift

static __device__ __forceinline__ unsigned long long u64min(unsigned long long a, unsigned long long b) {
    return a < b ? a : b;
}
static __device__ __forceinline__ unsigned long long u64max(unsigned long long a, unsigned long long b) {
    return a > b ? a : b;
}

// Kernel A: per-point NN search (stable argsort semantics) + derivative + partial sums.
__global__ __launch_bounds__(BLOCK_THREADS) void nn_kernel(
    const float* __restrict__ y, const float* __restrict__ x, float* __restrict__ out)
{
    __shared__ float sx[N_PTS];
    __shared__ float sy[N_PTS];
    __shared__ float s_d2[WARPS_PER_BLOCK];

    const int b      = blockIdx.x >> 8;       // /CHUNKS_PER_BATCH
    const int chunk  = blockIdx.x & 255;
    const int warpId = threadIdx.x >> 5;
    const int lane   = threadIdx.x & 31;
    const int p      = chunk * WARPS_PER_BLOCK + warpId;   // point index within batch

    const float* xb = x + b * N_PTS;
    const float* yb = y + b * N_PTS;
    #pragma unroll
    for (int i = threadIdx.x; i < N_PTS; i += BLOCK_THREADS) {
        sx[i] = xb[i];
        sy[i] = yb[i];
    }
    __syncthreads();

    // Candidate set: context points search context only; target p searches j <= p.
    const int nCand = (p < N_C) ? N_C : (p + 1);
    const float xi = sx[p];

    // Per-lane top-2 by key = (fp32 bits of dist, index). dist >= 0 so bit order
    // equals numeric order; low 32 bits give stable (index-ascending) tie-break,
    // matching jnp.argsort(stable) exactly.
    unsigned long long k1 = ~0ULL, k2 = ~0ULL;
    for (int j = lane; j < nCand; j += 32) {
        float dx = xi - sx[j];
        float dist = __fsqrt_rn(__fmul_rn(dx, dx));  // bit-exact vs jnp.linalg.norm (1D)
        unsigned long long key =
            ((unsigned long long)__float_as_uint(dist) << 32) | (unsigned int)j;
        if (key < k1)      { k2 = k1; k1 = key; }
        else if (key < k2) { k2 = key; }
    }
    // Warp tournament: merge sorted pairs {k1<=k2}.
    #pragma unroll
    for (int off = 16; off > 0; off >>= 1) {
        unsigned long long o1 = __shfl_down_sync(0xffffffffu, k1, off);
        unsigned long long o2 = __shfl_down_sync(0xffffffffu, k2, off);
        unsigned long long n1 = u64min(k1, o1);
        unsigned long long n2 = u64min(u64max(k1, o1), u64min(k2, o2));
        k1 = n1; k2 = n2;
    }

    if (lane == 0) {
        const int nn = (int)(unsigned int)(k2 & 0xffffffffULL);  // argsort[...,1]
        const float xcl  = sx[nn];
        const float ycl  = sy[nn];
        const float xrep = xi - xcl;
        const float yrep = sy[p] - ycl;
        const float nrm  = __fsqrt_rn(__fmul_rn(xrep, xrep));
        const float d    = __fdiv_rn(yrep, __fadd_rn(2e-6f, nrm));
        const float ad   = fabsf(d);
        const bool  clip = (ad > 200.0f);
        const float d2   = clip ? 0.0f : d;   // d_2 (and d_1 == d: no NaNs possible)
        const float lab  = clip ? 0.0f : 1.0f;

        const int g = b * N_PTS + p;
        out[OFF_YDIFF + g]        = yrep;
        out[OFF_XDIFF + g]        = xrep;
        out[OFF_DOUT + 2 * g]     = d2;    // raw; normalized in-place by kernel C
        out[OFF_DOUT + 2 * g + 1] = lab;
        out[OFF_XN + g]           = xcl;
        out[OFF_YN + g]           = ycl;
        s_d2[warpId] = d2;
    }
    __syncthreads();

    if (threadIdx.x == 0) {
        double s = 0.0, s2 = 0.0;
        #pragma unroll
        for (int w = 0; w < WARPS_PER_BLOCK; w++) {
            double v = (double)s_d2[w];
            s += v; s2 += v * v;
        }
        g_psum[blockIdx.x]  = s;
        g_psum2[blockIdx.x] = s2;
    }
}

// Kernel B: deterministic final reduce -> mean/var -> affine params.
__global__ void reduce_kernel(const float* __restrict__ bn_w, const float* __restrict__ bn_b) {
    __shared__ double ss[256];
    __shared__ double ss2[256];
    double s = 0.0, s2 = 0.0;
    for (int i = threadIdx.x; i < NUM_BLOCKS; i += 256) {
        s  += g_psum[i];
        s2 += g_psum2[i];
    }
    ss[threadIdx.x]  = s;
    ss2[threadIdx.x] = s2;
    __syncthreads();
    #pragma unroll
    for (int off = 128; off > 0; off >>= 1) {
        if (threadIdx.x < off) {
            ss[threadIdx.x]  += ss[threadIdx.x + off];
            ss2[threadIdx.x] += ss2[threadIdx.x + off];
        }
        __syncthreads();
    }
    if (threadIdx.x == 0) {
        const double n    = (double)N_TOTAL;
        const double mean = ss[0] / n;
        const double var  = ss2[0] / n - mean * mean;
        const double inv  = 1.0 / sqrt(var + 1e-5);
        const float scale = (float)inv * bn_w[0];
        g_affine[0] = scale;
        g_affine[1] = bn_b[0] - (float)mean * scale;
    }
}

// Kernel C: in-place normalize the d_norm slots.
__global__ void norm_kernel(float* __restrict__ out) {
    const int g = blockIdx.x * blockDim.x + threadIdx.x;
    if (g < N_TOTAL) {
        const float scale = g_affine[0];
        const float shift = g_affine[1];
        const int idx = OFF_DOUT + 2 * g;
        out[idx] = fmaf(out[idx], scale, shift);
    }
}

extern "C" void kernel_launch(void* const* d_in, const int* in_sizes, int n_in,
                              void* d_out, int out_size) {
    const float* y    = (const float*)d_in[0];
    const float* x    = (const float*)d_in[1];
    const float* bn_w = (const float*)d_in[2];
    const float* bn_b = (const float*)d_in[3];
    float* out = (float*)d_out;

    nn_kernel<<<NUM_BLOCKS, BLOCK_THREADS>>>(y, x, out);
    reduce_kernel<<<1, 256>>>(bn_w, bn_b);
    norm_kernel<<<(N_TOTAL + 255) / 256, 256>>>(out);
}

// round 2
// speedup vs baseline: 1.3355x; 1.3355x over previous
#include <cuda_runtime.h>

// Problem constants (fixed by setup_inputs)
#define N_PTS 2048
#define N_C   1024
#define B_SZ  8
#define WARPS_PER_BLOCK 8
#define BLOCK_THREADS   256
#define CHUNKS_PER_BATCH (N_PTS / WARPS_PER_BLOCK)        // 256
#define NUM_BLOCKS (B_SZ * CHUNKS_PER_BATCH)              // 2048
#define N_TOTAL (B_SZ * N_PTS)                            // 16384

// Output layout (tuple concat): y_diff | x_diff | d_out(B,N,2) | x_n | y_n
#define OFF_YDIFF 0
#define OFF_XDIFF (N_TOTAL)
#define OFF_DOUT  (2 * N_TOTAL)
#define OFF_XN    (4 * N_TOTAL)
#define OFF_YN    (5 * N_TOTAL)

// Deterministic reduction scratch (no device allocation allowed)
__device__ double g_psum[NUM_BLOCKS];
__device__ double g_psum2[NUM_BLOCKS];
__device__ int    g_count = 0;

typedef unsigned long long ull;

static __device__ __forceinline__ ull u64min(ull a, ull b) { return a < b ? a : b; }
static __device__ __forceinline__ ull u64max(ull a, ull b) { return a > b ? a : b; }

// Branch-free top-2 update: (v, j) against (v1,i1)/(v2,i2).
// Strict '<' + ascending-j processing order == stable-argsort tie-break per lane.
static __device__ __forceinline__ void top2_upd(
    float v, int j, float& v1, int& i1, float& v2, int& i2)
{
    const bool b1 = v < v1;
    const bool b2 = v < v2;
    i2 = b1 ? i1 : (b2 ? j : i2);
    v2 = b1 ? v1 : (b2 ? v : v2);
    i1 = b1 ? j : i1;
    v1 = b1 ? v : v1;
}

// Fused kernel: NN search + derivative + outputs + deterministic BN (last-block pattern).
__global__ __launch_bounds__(BLOCK_THREADS) void nn_fused_kernel(
    const float* __restrict__ y, const float* __restrict__ x,
    const float* __restrict__ bn_w, const float* __restrict__ bn_b,
    float* __restrict__ out)
{
    __shared__ float  sx[N_PTS];
    __shared__ float  sy[N_PTS];
    __shared__ float  s_d2[WARPS_PER_BLOCK];
    __shared__ double s_red[2 * BLOCK_THREADS];
    __shared__ float  s_affine[2];
    __shared__ int    s_islast;

    const int b      = blockIdx.x >> 8;       // / CHUNKS_PER_BATCH
    const int chunk  = blockIdx.x & 255;
    const int warpId = threadIdx.x >> 5;
    const int lane   = threadIdx.x & 31;
    const int p      = chunk * WARPS_PER_BLOCK + warpId;   // point index within batch

    // Vectorized smem fill
    {
        const float4* xb4 = (const float4*)(x + b * N_PTS);
        const float4* yb4 = (const float4*)(y + b * N_PTS);
        float4* sx4 = (float4*)sx;
        float4* sy4 = (float4*)sy;
        #pragma unroll
        for (int i = threadIdx.x; i < N_PTS / 4; i += BLOCK_THREADS) {
            sx4[i] = xb4[i];
            sy4[i] = yb4[i];
        }
    }
    __syncthreads();

    // Candidate set: context points search context only; target p searches j <= p.
    const int nCand = (p < N_C) ? N_C : (p + 1);
    const float xi = sx[p];

    // Per-lane top-2 by squared distance (monotone in the reference's sqrt dist).
    float v1 = __int_as_float(0x7f800000), v2 = v1;   // +inf
    int   i1 = 0x7fffffff, i2 = 0x7fffffff;

    const float4* sx4 = (const float4*)sx;
    const int nFull = nCand >> 7;                     // groups of 128 (32 lanes x 4)
    for (int g = 0; g < nFull; ++g) {
        const int j = (g << 7) + (lane << 2);
        const float4 xs = sx4[(g << 5) + lane];
        float d0 = xi - xs.x, d1 = xi - xs.y, d2 = xi - xs.z, d3 = xi - xs.w;
        top2_upd(d0 * d0, j,     v1, i1, v2, i2);
        top2_upd(d1 * d1, j + 1, v1, i1, v2, i2);
        top2_upd(d2 * d2, j + 2, v1, i1, v2, i2);
        top2_upd(d3 * d3, j + 3, v1, i1, v2, i2);
    }
    for (int j = (nFull << 7) + lane; j < nCand; j += 32) {
        const float dx = xi - sx[j];
        top2_upd(dx * dx, j, v1, i1, v2, i2);
    }

    // Cross-lane merge via u64 lexicographic keys (dist bits, index) -> stable tie-break.
    ull k1 = ((ull)__float_as_uint(v1) << 32) | (unsigned int)i1;
    ull k2 = ((ull)__float_as_uint(v2) << 32) | (unsigned int)i2;
    #pragma unroll
    for (int off = 16; off > 0; off >>= 1) {
        ull o1 = __shfl_down_sync(0xffffffffu, k1, off);
        ull o2 = __shfl_down_sync(0xffffffffu, k2, off);
        ull n1 = u64min(k1, o1);
        ull n2 = u64min(u64max(k1, o1), u64min(k2, o2));
        k1 = n1; k2 = n2;
    }

    if (lane == 0) {
        const int nn = (int)(unsigned int)(k2 & 0xffffffffULL);  // argsort[...,1]
        const float xcl  = sx[nn];
        const float ycl  = sy[nn];
        const float xrep = xi - xcl;
        const float yrep = sy[p] - ycl;
        const float nrm  = __fsqrt_rn(__fmul_rn(xrep, xrep));  // exact reference norm
        const float d    = __fdiv_rn(yrep, __fadd_rn(2e-6f, nrm));
        const bool  clip = (fabsf(d) > 200.0f);
        const float d2   = clip ? 0.0f : d;   // d_2 (d_1 == d: NaN impossible here)
        const float lab  = clip ? 0.0f : 1.0f;

        const int g = b * N_PTS + p;
        out[OFF_YDIFF + g]        = yrep;
        out[OFF_XDIFF + g]        = xrep;
        out[OFF_DOUT + 2 * g]     = d2;    // raw; normalized in-place below
        out[OFF_DOUT + 2 * g + 1] = lab;
        out[OFF_XN + g]           = xcl;
        out[OFF_YN + g]           = ycl;
        s_d2[warpId] = d2;
    }
    __syncthreads();

    // Per-block deterministic partial sums, then last-block-done handshake.
    if (threadIdx.x == 0) {
        double s = 0.0, s2 = 0.0;
        #pragma unroll
        for (int w = 0; w < WARPS_PER_BLOCK; w++) {
            double v = (double)s_d2[w];
            s += v; s2 += v * v;
        }
        g_psum[blockIdx.x]  = s;
        g_psum2[blockIdx.x] = s2;
        __threadfence();
        const int old = atomicAdd(&g_count, 1);
        s_islast = (old == NUM_BLOCKS - 1);
    }
    __syncthreads();

    if (!s_islast) return;

    // ---- Last block: final reduce + affine + in-place normalize ----
    __threadfence();  // acquire all other blocks' out[] and psum writes

    {
        double s = 0.0, s2 = 0.0;
        #pragma unroll
        for (int i = threadIdx.x; i < NUM_BLOCKS; i += BLOCK_THREADS) {
            s  += g_psum[i];
            s2 += g_psum2[i];
        }
        s_red[threadIdx.x]                 = s;
        s_red[BLOCK_THREADS + threadIdx.x] = s2;
    }
    __syncthreads();
    #pragma unroll
    for (int off = BLOCK_THREADS / 2; off > 0; off >>= 1) {
        if (threadIdx.x < off) {
            s_red[threadIdx.x]                 += s_red[threadIdx.x + off];
            s_red[BLOCK_THREADS + threadIdx.x] += s_red[BLOCK_THREADS + threadIdx.x + off];
        }
        __syncthreads();
    }
    if (threadIdx.x == 0) {
        const double n    = (double)N_TOTAL;
        const double mean = s_red[0] / n;
        const double var  = s_red[BLOCK_THREADS] / n - mean * mean;
        const double inv  = 1.0 / sqrt(var + 1e-5);
        const float scale = (float)inv * bn_w[0];
        s_affine[0] = scale;
        s_affine[1] = bn_b[0] - (float)mean * scale;
        g_count = 0;   // reset for next graph replay
    }
    __syncthreads();

    const float scale = s_affine[0];
    const float shift = s_affine[1];
    #pragma unroll
    for (int g = threadIdx.x; g < N_TOTAL; g += BLOCK_THREADS) {
        const int idx = OFF_DOUT + 2 * g;
        out[idx] = fmaf(out[idx], scale, shift);
    }
}

extern "C" void kernel_launch(void* const* d_in, const int* in_sizes, int n_in,
                              void* d_out, int out_size) {
    const float* y    = (const float*)d_in[0];
    const float* x    = (const float*)d_in[1];
    const float* bn_w = (const float*)d_in[2];
    const float* bn_b = (const float*)d_in[3];
    float* out = (float*)d_out;

    nn_fused_kernel<<<NUM_BLOCKS, BLOCK_THREADS>>>(y, x, bn_w, bn_b, out);
}